// round 1
// baseline (speedup 1.0000x reference)
#include <cuda_runtime.h>
#include <math.h>

// loss = max(2 * mean(a @ b.T), 1e-7)
// mean(a @ b.T) = (1/(N*M)) * sum_k colsum_a[k] * colsum_b[k]
// => two column-sum passes (HBM-bound, 64 MiB reads) + 512-elem dot.

#define N_ROWS 16384
#define K_COLS 512
#define K_VEC  (K_COLS / 4)          // 128 float4 per row
#define BLOCKS_PER_MAT 592           // 148 SMs * 4
#define TOTAL_BLOCKS (2 * BLOCKS_PER_MAT)

__device__ float g_colsum[2 * K_COLS];   // [0..511]=colsum(a), [512..1023]=colsum(b)

__global__ void qgc_zero_kernel() {
    int t = threadIdx.x;
    if (t < 2 * K_COLS) g_colsum[t] = 0.0f;
}

// 128 threads per block; thread t owns columns [4t, 4t+3].
// Each loop iteration reads one full 2KB row (perfectly coalesced float4).
__global__ void __launch_bounds__(128) qgc_colsum_kernel(
    const float* __restrict__ a, const float* __restrict__ b)
{
    const int mat = blockIdx.x & 1;
    const int bid = blockIdx.x >> 1;
    const float4* __restrict__ src =
        reinterpret_cast<const float4*>(mat ? b : a);
    const int t = threadIdx.x;

    float ax = 0.f, ay = 0.f, az = 0.f, aw = 0.f;

    #pragma unroll 4
    for (int r = bid; r < N_ROWS; r += BLOCKS_PER_MAT) {
        float4 v = src[(long)r * K_VEC + t];
        ax += v.x; ay += v.y; az += v.z; aw += v.w;
    }

    float* dst = g_colsum + mat * K_COLS + t * 4;
    atomicAdd(dst + 0, ax);
    atomicAdd(dst + 1, ay);
    atomicAdd(dst + 2, az);
    atomicAdd(dst + 3, aw);
}

// One block of 512 threads: dot(colsum_a, colsum_b) in fp64, scale, clamp.
__global__ void __launch_bounds__(512) qgc_final_kernel(float* __restrict__ out) {
    __shared__ double smem[16];
    const int t = threadIdx.x;

    double p = (double)g_colsum[t] * (double)g_colsum[K_COLS + t];

    // intra-warp reduce
    #pragma unroll
    for (int o = 16; o > 0; o >>= 1)
        p += __shfl_down_sync(0xffffffffu, p, o);

    if ((t & 31) == 0) smem[t >> 5] = p;
    __syncthreads();

    if (t < 16) {
        double v = smem[t];
        #pragma unroll
        for (int o = 8; o > 0; o >>= 1)
            v += __shfl_down_sync(0x0000ffffu, v, o);
        if (t == 0) {
            double loss = 2.0 * v / ((double)N_ROWS * (double)N_ROWS);
            if (loss < 1e-7) loss = 1e-7;
            out[0] = (float)loss;
        }
    }
}

extern "C" void kernel_launch(void* const* d_in, const int* in_sizes, int n_in,
                              void* d_out, int out_size) {
    const float* a = (const float*)d_in[0];
    const float* b = (const float*)d_in[1];
    float* out = (float*)d_out;

    qgc_zero_kernel<<<1, 1024>>>();
    qgc_colsum_kernel<<<TOTAL_BLOCKS, 128>>>(a, b);
    qgc_final_kernel<<<1, 512>>>(out);
}

// round 3
// speedup vs baseline: 1.0010x; 1.0010x over previous
#include <cuda_runtime.h>

// loss = max(2 * mean(a @ b.T), 1e-7)
// mean(a @ b.T) = (1/(N*M)) * sum_k colsum_a[k] * colsum_b[k]
// Single fused persistent kernel: column sums (HBM-bound, 64 MiB reads)
// + last-block fp64 dot + self-reset for graph replays.

#define N_ROWS 16384
#define KV 128                     // float4 per row (K=512)
#define TPB 256
#define BLOCKS_PER_MAT 592
#define TOTAL_BLOCKS (2 * BLOCKS_PER_MAT)   // 1184 ~= 8 blocks/SM
#define ROWS_PER_ITER (BLOCKS_PER_MAT * 2)  // 2 rows per block-iteration

__device__ float g_colsum[1024];   // [0..511]=colsum(a), [512..1023]=colsum(b)
__device__ unsigned int g_count;   // arrival counter (zero-init, reset each run)

__global__ void __launch_bounds__(TPB) qgc_fused(
    const float* __restrict__ a, const float* __restrict__ b,
    float* __restrict__ out)
{
    __shared__ float   s_red[TPB * 4];   // 4 KB block-level partials
    __shared__ unsigned s_rank;
    __shared__ double  s_warp[8];

    const int mat = blockIdx.x & 1;
    const int bid = blockIdx.x >> 1;
    const float4* __restrict__ src =
        reinterpret_cast<const float4*>(mat ? b : a);
    const int t    = threadIdx.x;
    const int col  = t & (KV - 1);   // float4 column 0..127
    const int rsub = t >> 7;         // row sub-index 0..1

    // ---- phase 1: column partial sums (coalesced, streaming) ----
    float ax = 0.f, ay = 0.f, az = 0.f, aw = 0.f;
    #pragma unroll 4
    for (int r = bid * 2 + rsub; r < N_ROWS; r += ROWS_PER_ITER) {
        float4 v = __ldcs(src + (long)r * KV + col);
        ax += v.x; ay += v.y; az += v.z; aw += v.w;
    }

    s_red[t * 4 + 0] = ax;
    s_red[t * 4 + 1] = ay;
    s_red[t * 4 + 2] = az;
    s_red[t * 4 + 3] = aw;
    __syncthreads();

    // ---- phase 2: block reduce (2 row-groups) + global atomic accumulate ----
    if (t < KV) {
        float* base = g_colsum + mat * 512 + t * 4;
        #pragma unroll
        for (int j = 0; j < 4; j++) {
            float s = s_red[t * 4 + j] + s_red[(KV + t) * 4 + j];
            atomicAdd(base + j, s);      // RED.ADD.F32, no return
        }
        __threadfence();
    }
    __syncthreads();
    if (t == 0) s_rank = atomicAdd(&g_count, 1u);
    __syncthreads();

    // ---- phase 3: last-arriving block computes the dot, writes out, resets ----
    if (s_rank == TOTAL_BLOCKS - 1) {
        __threadfence();
        // 512 columns over 256 threads, fp64 accumulation, L2-coherent reads
        double p = (double)__ldcg(&g_colsum[t])       * (double)__ldcg(&g_colsum[512 + t])
                 + (double)__ldcg(&g_colsum[256 + t]) * (double)__ldcg(&g_colsum[768 + t]);

        #pragma unroll
        for (int o = 16; o > 0; o >>= 1)
            p += __shfl_down_sync(0xffffffffu, p, o);
        if ((t & 31) == 0) s_warp[t >> 5] = p;
        __syncthreads();

        if (t < 8) {
            double v = s_warp[t];
            #pragma unroll
            for (int o = 4; o > 0; o >>= 1)
                v += __shfl_down_sync(0x000000ffu, v, o);
            if (t == 0) {
                double loss = 2.0 * v / ((double)N_ROWS * (double)N_ROWS);
                out[0] = (float)(loss < 1e-7 ? 1e-7 : loss);
            }
        }
        __syncthreads();

        // reset scratch so the next graph replay starts clean
        g_colsum[t]       = 0.f;
        g_colsum[256 + t] = 0.f;
        g_colsum[512 + t] = 0.f;
        g_colsum[768 + t] = 0.f;
        if (t == 0) g_count = 0u;
    }
}

extern "C" void kernel_launch(void* const* d_in, const int* in_sizes, int n_in,
                              void* d_out, int out_size) {
    const float* a = (const float*)d_in[0];
    const float* b = (const float*)d_in[1];
    float* out = (float*)d_out;

    qgc_fused<<<TOTAL_BLOCKS, TPB>>>(a, b, out);
}